// round 1
// baseline (speedup 1.0000x reference)
#include <cuda_runtime.h>
#include <math.h>

#define NT   128   // threads per CTA (one per hidden neuron)
#define BSUB 8     // batch rows per CTA
#define TT   128   // time points
#define DD   256   // dense grid size
#define HW   128   // hidden width

// concentration interp on uniform grid dense_ts = arange(DD)
__device__ __forceinline__ float interp_c(float t, const float* __restrict__ row) {
    int i = (int)ceilf(t);
    i = i < 1 ? 1 : (i > DD - 1 ? DD - 1 : i);
    float w = t - (float)(i - 1);
    w = fminf(fmaxf(w, 0.f), 1.f);
    return (1.f - w) * row[i - 1] + w * row[i];
}

__global__ __launch_bounds__(NT, 1)
void ode_kernel(const float* __restrict__ ts, const float* __restrict__ y0,
                const float* __restrict__ latent, const int* __restrict__ length,
                const float* __restrict__ dts, const float* __restrict__ dcs,
                const float* __restrict__ W1, const float* __restrict__ b1,
                const float* __restrict__ W2, const float* __restrict__ b2,
                const float* __restrict__ W3, const float* __restrict__ b3,
                float* __restrict__ out)
{
    extern __shared__ float sm[];
    float* W2t    = sm;               // [128][128]  W2t[k*128+o] = W2[o][k]
    float* W3t    = W2t + HW * HW;    // [128][9]    W3t[k*9+o]  = W3[o][k], o<9
    float* h1s    = W3t + HW * 9;     // [8][128]
    float* h2s    = h1s + BSUB * HW;  // [8][128]
    float* bpre   = h2s + BSUB * HW;  // [8][128]  b1 + W1[:,9:41] @ latent[r]
    float* csS    = bpre + BSUB * HW; // [8][256]  dense_cs rows
    float* tsS    = csS + BSUB * DD;  // [128]
    float* Ybase  = tsS + TT;         // [72]  state (9 dims x 8 rows)
    float* Ystage = Ybase + 72;       // [72]
    float* Yacc   = Ystage + 72;      // [72]
    float* cS     = Yacc + 72;        // [8]
    float* b3s    = cS + 8;           // [12] (padded)
    float* tendS  = b3s + 12;         // [8]

    const int tid = threadIdx.x;
    const int r0  = blockIdx.x * BSUB;

    // ---- one-time setup ----
    for (int i = tid; i < HW * HW; i += NT) {       // coalesced read, transposed write
        int o = i >> 7, k = i & 127;
        W2t[k * HW + o] = W2[i];
    }
    for (int i = tid; i < 9 * HW; i += NT) {
        int o = i >> 7, k = i & 127;
        W3t[k * 9 + o] = W3[i];
    }
    for (int i = tid; i < BSUB * DD; i += NT) {
        int r = i >> 8;
        csS[i] = dcs[(r0 + r) * DD + (i & 255)];
    }
    tsS[tid] = ts[tid];
    if (tid < 9) b3s[tid] = b3[tid];
    if (tid < BSUB) {
        int len = length[r0 + tid];
        int idx = len - 1; if (idx < 0) idx = 0;
        tendS[tid] = ts[idx];
        out[(r0 + tid) * TT] = y0[r0 + tid];        // save t=0
    }
    if (tid < 72) {
        int r = tid / 9, j = tid - r * 9;
        float v = (j == 0) ? y0[r0 + r] : 0.f;
        Ybase[tid] = v;
        Yacc[tid]  = v;
    }

    // per-thread layer-1 weights (varying inputs only) + latent precompute
    float w1r[9], w1t, w1c, b2n;
    {
        const float* w = W1 + tid * 43;
        #pragma unroll
        for (int j = 0; j < 9; ++j) w1r[j] = w[j];
        w1t = w[41];
        w1c = w[42];
        b2n = b2[tid];
        float bb = b1[tid];
        #pragma unroll 2
        for (int r = 0; r < BSUB; ++r) {
            float a = bb;
            const float* lat = latent + (r0 + r) * 32;
            #pragma unroll
            for (int j = 0; j < 32; ++j) a += w[9 + j] * lat[j];
            bpre[r * HW + tid] = a;
        }
    }
    __syncthreads();

    const float A[4]  = {0.f, 0.5f, 0.5f, 1.f};
    const float Wc[4] = {1.f, 2.f, 2.f, 1.f};

    // ---- main sequential time loop ----
    for (int n = 0; n < TT - 1; ++n) {
        float t0  = tsS[n];
        float dtf = (tsS[n + 1] - t0) * 0.5f;       // SUB = 2
        for (int sub = 0; sub < 2; ++sub) {
            float tstart = t0 + (float)sub * dtf;
            if (tid < 72) Ystage[tid] = Ybase[tid];
            if (tid < BSUB) cS[tid] = interp_c(tstart, csS + tid * DD);
            __syncthreads();

            #pragma unroll
            for (int s = 0; s < 4; ++s) {
                float tt  = tstart + A[s] * dtf;
                float wgt = dtf * (1.f / 6.f) * Wc[s];

                // ---- layer 1: thread = neuron, loop rows ----
                #pragma unroll
                for (int r = 0; r < BSUB; ++r) {
                    float a = bpre[r * HW + tid] + w1t * tt + w1c * cS[r];
                    #pragma unroll
                    for (int j = 0; j < 9; ++j) a += w1r[j] * Ystage[r * 9 + j];
                    h1s[r * HW + tid] = tanhf(a);
                }
                __syncthreads();

                // ---- layer 2: 1024 FFMA/thread, W2 read once, h broadcast f4 ----
                float acc[BSUB];
                #pragma unroll
                for (int r = 0; r < BSUB; ++r) acc[r] = b2n;
                for (int k = 0; k < HW; k += 4) {
                    float wv0 = W2t[(k + 0) * HW + tid];
                    float wv1 = W2t[(k + 1) * HW + tid];
                    float wv2 = W2t[(k + 2) * HW + tid];
                    float wv3 = W2t[(k + 3) * HW + tid];
                    #pragma unroll
                    for (int r = 0; r < BSUB; ++r) {
                        const float4 hv = *reinterpret_cast<const float4*>(&h1s[r * HW + k]);
                        acc[r] += wv0 * hv.x + wv1 * hv.y + wv2 * hv.z + wv3 * hv.w;
                    }
                }
                #pragma unroll
                for (int r = 0; r < BSUB; ++r) h2s[r * HW + tid] = tanhf(acc[r]);
                __syncthreads();

                // ---- layer 3 (only 9 outputs matter) + RK4 accumulate + next-stage state ----
                if (tid < 72) {
                    int r = tid / 9, o = tid - r * 9;
                    float a = b3s[o];
                    const float* h2r = h2s + r * HW;
                    #pragma unroll 8
                    for (int k = 0; k < HW; ++k) a += h2r[k] * W3t[k * 9 + o];
                    if (o == 0) a = -cosf(a);
                    if (tt > tendS[r]) a = 0.f;
                    Yacc[tid] += wgt * a;
                    if (s < 3) Ystage[tid] = Ybase[tid] + (A[s + 1] * dtf) * a;
                }
                if (tid < BSUB && s < 3)
                    cS[tid] = interp_c(tstart + A[s + 1] * dtf, csS + tid * DD);
                __syncthreads();
            }

            if (tid < 72) Ybase[tid] = Yacc[tid];   // commit substep
            __syncthreads();
        }
        if (tid < BSUB) out[(r0 + tid) * TT + n + 1] = Ybase[tid * 9];
    }
}

extern "C" void kernel_launch(void* const* d_in, const int* in_sizes, int n_in,
                              void* d_out, int out_size) {
    const float* ts     = (const float*)d_in[0];
    const float* y0     = (const float*)d_in[1];
    const float* latent = (const float*)d_in[2];
    const int*   length = (const int*)  d_in[3];
    const float* dts    = (const float*)d_in[4];
    const float* dcs    = (const float*)d_in[5];
    const float* W1     = (const float*)d_in[6];
    const float* b1     = (const float*)d_in[7];
    const float* W2     = (const float*)d_in[8];
    const float* b2     = (const float*)d_in[9];
    const float* W3     = (const float*)d_in[10];
    const float* b3     = (const float*)d_in[11];
    float* out = (float*)d_out;

    const size_t smem_floats = 16384 + 1152 + 1024 + 1024 + 1024 + 2048 + 128
                             + 72 + 72 + 72 + 8 + 12 + 8;
    const size_t smem = smem_floats * sizeof(float);  // 92112 bytes
    cudaFuncSetAttribute(ode_kernel, cudaFuncAttributeMaxDynamicSharedMemorySize, (int)smem);

    ode_kernel<<<128, NT, smem>>>(ts, y0, latent, length, dts, dcs,
                                  W1, b1, W2, b2, W3, b3, out);
}

// round 2
// speedup vs baseline: 1.3902x; 1.3902x over previous
#include <cuda_runtime.h>
#include <math.h>

#define NT   256   // threads per CTA: 2 warps/SMSP
#define BSUB 8     // batch rows per CTA
#define TT   128
#define DD   256
#define HW   128
#define W2S  132   // padded stride for W2 (conflict-free float4 row loads)

__device__ __forceinline__ float tanha(float x) {
    float y; asm("tanh.approx.f32 %0, %1;" : "=f"(y) : "f"(x)); return y;
}
#define FFMA2(acc, a, b) \
    asm("fma.rn.f32x2 %0, %1, %2, %3;" : "=l"(acc) : "l"(a), "l"(b), "l"(acc))

__device__ __forceinline__ float interp_c(float t, const float* __restrict__ row) {
    int i = (int)ceilf(t);
    i = i < 1 ? 1 : (i > DD - 1 ? DD - 1 : i);
    float w = t - (float)(i - 1);
    w = fminf(fmaxf(w, 0.f), 1.f);
    return (1.f - w) * row[i - 1] + w * row[i];
}

__global__ __launch_bounds__(NT, 1)
void ode_kernel(const float* __restrict__ ts, const float* __restrict__ y0,
                const float* __restrict__ latent, const int* __restrict__ length,
                const float* __restrict__ dts, const float* __restrict__ dcs,
                const float* __restrict__ W1, const float* __restrict__ b1,
                const float* __restrict__ W2, const float* __restrict__ b2,
                const float* __restrict__ W3, const float* __restrict__ b3,
                float* __restrict__ out)
{
    extern __shared__ float sm[];
    float* W2v    = sm;                 // [128][132]  W2v[o*132+k] = W2[o][k]
    float* W3t    = W2v + HW * W2S;     // [128][9]    W3t[k*9+o]  = W3[o][k], o<9
    float* h1s    = W3t + 1152;         // [8][128]
    float* h2s    = h1s + BSUB * HW;    // [8][128]
    float* bpre   = h2s + BSUB * HW;    // [8][128]
    float* csS    = bpre + BSUB * HW;   // [8][256]
    float* tsS    = csS + BSUB * DD;    // [128]
    float* Ybase  = tsS + TT;           // [72]
    float* Ystage = Ybase + 72;         // [72]
    float* Yacc   = Ystage + 72;        // [72]
    float* cS     = Yacc + 72;          // [8]
    float* b3s    = cS + 8;             // [12]
    float* tendS  = b3s + 12;           // [8]

    const int tid = threadIdx.x;
    const int o   = tid & 127;          // neuron
    const int g   = tid >> 7;           // row group (rows 4g..4g+3)
    const int r0  = blockIdx.x * BSUB;

    // ---- one-time setup ----
    for (int i = tid; i < HW * HW; i += NT) {
        int oo = i >> 7, k = i & 127;
        W2v[oo * W2S + k] = W2[i];
    }
    for (int i = tid; i < 9 * HW; i += NT) {
        int oo = i >> 7, k = i & 127;
        W3t[k * 9 + oo] = W3[i];
    }
    for (int i = tid; i < BSUB * DD; i += NT) {
        int r = i >> 8;
        csS[i] = dcs[(r0 + r) * DD + (i & 255)];
    }
    if (tid < TT) tsS[tid] = ts[tid];
    if (tid < 9)  b3s[tid] = b3[tid];
    if (tid < BSUB) {
        int len = length[r0 + tid];
        int idx = len - 1; if (idx < 0) idx = 0;
        tendS[tid] = ts[idx];
        out[(r0 + tid) * TT] = y0[r0 + tid];
    }
    if (tid < 72) {
        int r = tid / 9, j = tid - r * 9;
        float v = (j == 0) ? y0[r0 + r] : 0.f;
        Ybase[tid] = v;
        Yacc[tid]  = v;
    }

    // per-thread layer-1 weights + latent precompute (each g does its 4 rows)
    float w1r[9], w1t, w1c, b2n;
    {
        const float* w = W1 + o * 43;
        #pragma unroll
        for (int j = 0; j < 9; ++j) w1r[j] = w[j];
        w1t = w[41];
        w1c = w[42];
        b2n = b2[o];
        float bb = b1[o];
        for (int rr = 0; rr < 4; ++rr) {
            int r = 4 * g + rr;
            float a = bb;
            const float* lat = latent + (r0 + r) * 32;
            #pragma unroll
            for (int j = 0; j < 32; ++j) a += w[9 + j] * lat[j];
            bpre[r * HW + o] = a;
        }
    }
    __syncthreads();

    const float A[4]  = {0.f, 0.5f, 0.5f, 1.f};
    const float Wc[4] = {1.f, 2.f, 2.f, 1.f};
    const int row = tid >> 5;           // warp id 0..7 -> batch row (layer 3)
    const int l   = tid & 31;

    for (int n = 0; n < TT - 1; ++n) {
        float t0  = tsS[n];
        float dtf = (tsS[n + 1] - t0) * 0.5f;       // SUB = 2
        for (int sub = 0; sub < 2; ++sub) {
            float tstart = t0 + (float)sub * dtf;
            if (tid < 72) Ystage[tid] = Ybase[tid];
            if (tid < BSUB) cS[tid] = interp_c(tstart, csS + tid * DD);
            __syncthreads();

            #pragma unroll
            for (int s = 0; s < 4; ++s) {
                float tt  = tstart + A[s] * dtf;
                float wgt = dtf * (1.f / 6.f) * Wc[s];

                // ---- layer 1: thread = (neuron, row-group) ----
                #pragma unroll
                for (int rr = 0; rr < 4; ++rr) {
                    int r = 4 * g + rr;
                    float a = bpre[r * HW + o] + w1t * tt + w1c * cS[r];
                    #pragma unroll
                    for (int j = 0; j < 9; ++j) a += w1r[j] * Ystage[r * 9 + j];
                    h1s[r * HW + o] = tanha(a);
                }
                __syncthreads();

                // ---- layer 2: packed f32x2 FFMA, 4 rows per thread ----
                {
                    unsigned long long acc[4] = {0ull, 0ull, 0ull, 0ull};
                    const float* wrow = W2v + o * W2S;
                    const float* hb   = h1s + 4 * g * HW;
                    #pragma unroll 4
                    for (int k = 0; k < HW; k += 4) {
                        ulonglong2 wv = *reinterpret_cast<const ulonglong2*>(wrow + k);
                        ulonglong2 h0 = *reinterpret_cast<const ulonglong2*>(hb + 0 * HW + k);
                        ulonglong2 h1 = *reinterpret_cast<const ulonglong2*>(hb + 1 * HW + k);
                        ulonglong2 h2 = *reinterpret_cast<const ulonglong2*>(hb + 2 * HW + k);
                        ulonglong2 h3 = *reinterpret_cast<const ulonglong2*>(hb + 3 * HW + k);
                        FFMA2(acc[0], wv.x, h0.x); FFMA2(acc[0], wv.y, h0.y);
                        FFMA2(acc[1], wv.x, h1.x); FFMA2(acc[1], wv.y, h1.y);
                        FFMA2(acc[2], wv.x, h2.x); FFMA2(acc[2], wv.y, h2.y);
                        FFMA2(acc[3], wv.x, h3.x); FFMA2(acc[3], wv.y, h3.y);
                    }
                    #pragma unroll
                    for (int rr = 0; rr < 4; ++rr) {
                        float lo, hi;
                        asm("mov.b64 {%0,%1}, %2;" : "=f"(lo), "=f"(hi) : "l"(acc[rr]));
                        h2s[(4 * g + rr) * HW + o] = tanha(lo + hi + b2n);
                    }
                }
                __syncthreads();

                // ---- layer 3: warp-per-row, shuffle reduction ----
                {
                    float acc9[9];
                    #pragma unroll
                    for (int o2 = 0; o2 < 9; ++o2) acc9[o2] = 0.f;
                    const float* h2r = h2s + row * HW;
                    #pragma unroll
                    for (int j = 0; j < 4; ++j) {
                        int k = j * 32 + l;
                        float h = h2r[k];
                        #pragma unroll
                        for (int o2 = 0; o2 < 9; ++o2)
                            acc9[o2] += h * W3t[k * 9 + o2];
                    }
                    #pragma unroll
                    for (int off = 16; off > 0; off >>= 1) {
                        #pragma unroll
                        for (int o2 = 0; o2 < 9; ++o2)
                            acc9[o2] += __shfl_down_sync(0xffffffffu, acc9[o2], off);
                    }
                    if (l == 0) {
                        bool stop = (tt > tendS[row]);
                        float stg = A[(s + 1) & 3] * dtf;
                        #pragma unroll
                        for (int o2 = 0; o2 < 9; ++o2) {
                            float a = acc9[o2] + b3s[o2];
                            if (o2 == 0) a = -cosf(a);
                            if (stop) a = 0.f;
                            Yacc[row * 9 + o2] += wgt * a;
                            if (s < 3)
                                Ystage[row * 9 + o2] = Ybase[row * 9 + o2] + stg * a;
                        }
                    }
                    if (l == 16 && s < 3)
                        cS[row] = interp_c(tstart + A[s + 1] * dtf, csS + row * DD);
                }
                __syncthreads();
            }

            if (tid < 72) Ybase[tid] = Yacc[tid];
            __syncthreads();
        }
        if (tid < BSUB) out[(r0 + tid) * TT + n + 1] = Ybase[tid * 9];
    }
}

extern "C" void kernel_launch(void* const* d_in, const int* in_sizes, int n_in,
                              void* d_out, int out_size) {
    const float* ts     = (const float*)d_in[0];
    const float* y0     = (const float*)d_in[1];
    const float* latent = (const float*)d_in[2];
    const int*   length = (const int*)  d_in[3];
    const float* dts    = (const float*)d_in[4];
    const float* dcs    = (const float*)d_in[5];
    const float* W1     = (const float*)d_in[6];
    const float* b1     = (const float*)d_in[7];
    const float* W2     = (const float*)d_in[8];
    const float* b2     = (const float*)d_in[9];
    const float* W3     = (const float*)d_in[10];
    const float* b3     = (const float*)d_in[11];
    float* out = (float*)d_out;

    const size_t smem_floats = (size_t)HW * W2S + 1152
                             + 3 * (size_t)BSUB * HW + (size_t)BSUB * DD + TT
                             + 3 * 72 + 8 + 12 + 8;
    const size_t smem = smem_floats * sizeof(float);   // 94160 bytes
    cudaFuncSetAttribute(ode_kernel, cudaFuncAttributeMaxDynamicSharedMemorySize, (int)smem);

    ode_kernel<<<128, NT, smem>>>(ts, y0, latent, length, dts, dcs,
                                  W1, b1, W2, b2, W3, b3, out);
}

// round 3
// speedup vs baseline: 1.4215x; 1.0225x over previous
#include <cuda_runtime.h>
#include <math.h>

#define NT   512   // 16 warps: thread = (neuron o, k-quarter q)
#define BSUB 8     // batch rows per CTA
#define TT   128
#define DD   256
#define HW   128

__device__ __forceinline__ float tanha(float x) {
    float y; asm("tanh.approx.f32 %0, %1;" : "=f"(y) : "f"(x)); return y;
}
#define FFMA2(acc, a, b) \
    asm("fma.rn.f32x2 %0, %1, %2, %3;" : "=l"(acc) : "l"(a), "l"(b), "l"(acc))

__device__ __forceinline__ float interp_c(float t, const float* __restrict__ row) {
    int i = (int)ceilf(t);
    i = i < 1 ? 1 : (i > DD - 1 ? DD - 1 : i);
    float w = t - (float)(i - 1);
    w = fminf(fmaxf(w, 0.f), 1.f);
    return (1.f - w) * row[i - 1] + w * row[i];
}

__global__ __launch_bounds__(NT, 1)
void ode_kernel(const float* __restrict__ ts, const float* __restrict__ y0,
                const float* __restrict__ latent, const int* __restrict__ length,
                const float* __restrict__ dts, const float* __restrict__ dcs,
                const float* __restrict__ W1, const float* __restrict__ b1,
                const float* __restrict__ W2, const float* __restrict__ b2,
                const float* __restrict__ W3, const float* __restrict__ b3,
                float* __restrict__ out)
{
    extern __shared__ float sm[];
    float* W3t    = sm;                 // [128][9]  W3t[k*9+o] = W3[o][k], o<9
    float* h1s    = W3t + 1152;         // [8][128]
    float* pS     = h1s + BSUB * HW;    // [4][8][128] layer-2 partial sums
    float* bpre   = pS + 4 * BSUB * HW; // [8][128]
    float* csS    = bpre + BSUB * HW;   // [8][256]
    float* tsS    = csS + BSUB * DD;    // [128]
    float* b2s    = tsS + TT;           // [128]
    float* Ybase  = b2s + HW;           // [72]
    float* Ystage = Ybase + 72;         // [72]
    float* Yacc   = Ystage + 72;        // [72]
    float* cS     = Yacc + 72;          // [8]
    float* b3s    = cS + 8;             // [12]
    float* tendS  = b3s + 12;           // [8]

    const int tid = threadIdx.x;
    const int o   = tid & 127;          // neuron index
    const int q   = tid >> 7;           // k-quarter 0..3
    const int r0  = blockIdx.x * BSUB;

    // ---- one-time setup ----
    for (int i = tid; i < 9 * HW; i += NT) {
        int oo = i >> 7, k = i & 127;
        W3t[k * 9 + oo] = W3[i];
    }
    for (int i = tid; i < BSUB * DD; i += NT) {
        int r = i >> 8;
        csS[i] = dcs[(r0 + r) * DD + (i & 255)];
    }
    if (tid < TT) tsS[tid] = ts[tid];
    if (tid < HW) b2s[tid] = b2[tid];
    if (tid < 9)  b3s[tid] = b3[tid];
    if (tid < BSUB) {
        int len = length[r0 + tid];
        int idx = len - 1; if (idx < 0) idx = 0;
        tendS[tid] = ts[idx];
        out[(r0 + tid) * TT] = y0[r0 + tid];
    }
    if (tid < 72) {
        int r = tid / 9, j = tid - r * 9;
        float v = (j == 0) ? y0[r0 + r] : 0.f;
        Ybase[tid] = v;
        Yacc[tid]  = v;
    }

    // ---- per-thread register-resident weights ----
    // W2 slice: W2[o][32q .. 32q+31] as 16 packed f32x2
    unsigned long long w2p[16];
    {
        const float* wr = W2 + o * HW + 32 * q;
        #pragma unroll
        for (int j = 0; j < 16; ++j) {
            float lo = wr[2 * j], hi = wr[2 * j + 1];
            asm("mov.b64 %0, {%1,%2};" : "=l"(w2p[j]) : "f"(lo), "f"(hi));
        }
    }
    // layer-1 weights (shared by this thread's two rows) + latent precompute
    float w1r[9], w1t, w1c;
    {
        const float* w = W1 + o * 43;
        #pragma unroll
        for (int j = 0; j < 9; ++j) w1r[j] = w[j];
        w1t = w[41];
        w1c = w[42];
        float bb = b1[o];
        #pragma unroll
        for (int rr = 0; rr < 2; ++rr) {
            int r = 2 * q + rr;
            float a = bb;
            const float* lat = latent + (r0 + r) * 32;
            #pragma unroll
            for (int j = 0; j < 32; ++j) a += w[9 + j] * lat[j];
            bpre[r * HW + o] = a;
        }
    }
    __syncthreads();

    const float A[4]  = {0.f, 0.5f, 0.5f, 1.f};
    const float Wc[4] = {1.f, 2.f, 2.f, 1.f};
    const int wid = tid >> 5;           // warp 0..15
    const int l   = tid & 31;

    for (int n = 0; n < TT - 1; ++n) {
        float t0  = tsS[n];
        float dtf = (tsS[n + 1] - t0) * 0.5f;       // SUB = 2
        #pragma unroll 1
        for (int sub = 0; sub < 2; ++sub) {
            float tstart = t0 + (float)sub * dtf;
            if (tid < 72) Ystage[tid] = Ybase[tid];
            if (tid < BSUB) cS[tid] = interp_c(tstart, csS + tid * DD);
            __syncthreads();

            #pragma unroll
            for (int s = 0; s < 4; ++s) {
                float tt  = tstart + A[s] * dtf;
                float wgt = dtf * (1.f / 6.f) * Wc[s];

                // ---- layer 1: thread (o,q) does rows 2q, 2q+1 ----
                #pragma unroll
                for (int rr = 0; rr < 2; ++rr) {
                    int r = 2 * q + rr;
                    float a = bpre[r * HW + o] + w1t * tt + w1c * cS[r];
                    #pragma unroll
                    for (int j = 0; j < 9; ++j) a += w1r[j] * Ystage[r * 9 + j];
                    h1s[r * HW + o] = tanha(a);
                }
                __syncthreads();

                // ---- layer 2: W2 in regs, h1 broadcast loads, 8 rows ----
                {
                    unsigned long long acc[BSUB];
                    #pragma unroll
                    for (int r = 0; r < BSUB; ++r) acc[r] = 0ull;
                    const float* hb = h1s + 32 * q;
                    #pragma unroll 2
                    for (int j = 0; j < 8; ++j) {          // 8 x ulonglong2 = 32 k
                        #pragma unroll
                        for (int r = 0; r < BSUB; ++r) {
                            ulonglong2 hv = *reinterpret_cast<const ulonglong2*>(hb + r * HW + 4 * j);
                            FFMA2(acc[r], w2p[2 * j],     hv.x);
                            FFMA2(acc[r], w2p[2 * j + 1], hv.y);
                        }
                    }
                    float* pq = pS + q * (BSUB * HW) + o;
                    #pragma unroll
                    for (int r = 0; r < BSUB; ++r) {
                        float lo, hi;
                        asm("mov.b64 {%0,%1}, %2;" : "=f"(lo), "=f"(hi) : "l"(acc[r]));
                        pq[r * HW] = lo + hi;
                    }
                }
                __syncthreads();

                // ---- layer 3: warp-per-row (warps 0-7); combine partials + tanh here ----
                if (wid < BSUB) {
                    const int r = wid;
                    float acc9[9];
                    #pragma unroll
                    for (int o2 = 0; o2 < 9; ++o2) acc9[o2] = 0.f;
                    const float* pr = pS + r * HW;
                    #pragma unroll
                    for (int j = 0; j < 4; ++j) {
                        int k = j * 32 + l;
                        float v = pr[k] + pr[1024 + k] + pr[2048 + k] + pr[3072 + k] + b2s[k];
                        float h = tanha(v);
                        #pragma unroll
                        for (int o2 = 0; o2 < 9; ++o2)
                            acc9[o2] += h * W3t[k * 9 + o2];
                    }
                    #pragma unroll
                    for (int off = 16; off > 0; off >>= 1) {
                        #pragma unroll
                        for (int o2 = 0; o2 < 9; ++o2)
                            acc9[o2] += __shfl_down_sync(0xffffffffu, acc9[o2], off);
                    }
                    if (l == 0) {
                        bool stop = (tt > tendS[r]);
                        float stg = A[(s + 1) & 3] * dtf;
                        #pragma unroll
                        for (int o2 = 0; o2 < 9; ++o2) {
                            float a = acc9[o2] + b3s[o2];
                            if (o2 == 0) a = -cosf(a);
                            if (stop) a = 0.f;
                            Yacc[r * 9 + o2] += wgt * a;
                            if (s < 3)
                                Ystage[r * 9 + o2] = Ybase[r * 9 + o2] + stg * a;
                        }
                    }
                    if (l == 16 && s < 3)
                        cS[r] = interp_c(tstart + A[s + 1] * dtf, csS + r * DD);
                }
                __syncthreads();
            }

            if (tid < 72) Ybase[tid] = Yacc[tid];
            __syncthreads();
        }
        if (tid < BSUB) out[(r0 + tid) * TT + n + 1] = Ybase[tid * 9];
    }
}

extern "C" void kernel_launch(void* const* d_in, const int* in_sizes, int n_in,
                              void* d_out, int out_size) {
    const float* ts     = (const float*)d_in[0];
    const float* y0     = (const float*)d_in[1];
    const float* latent = (const float*)d_in[2];
    const int*   length = (const int*)  d_in[3];
    const float* dts    = (const float*)d_in[4];
    const float* dcs    = (const float*)d_in[5];
    const float* W1     = (const float*)d_in[6];
    const float* b1     = (const float*)d_in[7];
    const float* W2     = (const float*)d_in[8];
    const float* b2     = (const float*)d_in[9];
    const float* W3     = (const float*)d_in[10];
    const float* b3     = (const float*)d_in[11];
    float* out = (float*)d_out;

    const size_t smem_floats = 1152 + (size_t)BSUB * HW + 4 * (size_t)BSUB * HW
                             + (size_t)BSUB * HW + (size_t)BSUB * DD + TT + HW
                             + 3 * 72 + 8 + 12 + 8;
    const size_t smem = smem_floats * sizeof(float);   // ~39 KB
    cudaFuncSetAttribute(ode_kernel, cudaFuncAttributeMaxDynamicSharedMemorySize, (int)smem);

    ode_kernel<<<128, NT, smem>>>(ts, y0, latent, length, dts, dcs,
                                  W1, b1, W2, b2, W3, b3, out);
}